// round 2
// baseline (speedup 1.0000x reference)
#include <cuda_runtime.h>

// Problem-size capacities (N=100000, E=1000000 in this dataset)
#define MAXN 100352
#define MAXE 1000448
#define SCAN_BS 512
#define MAXNB ((MAXN + SCAN_BS - 1) / SCAN_BS)   // 196 <= 256
#define AGG_WARPS 8
#define MAXBLK ((MAXN + AGG_WARPS - 1) / AGG_WARPS)

// ---- device scratch (static: no allocations allowed) ----
__device__ int    g_deg[MAXN];          // degree, then scatter cursor
__device__ int    g_off[MAXN + 1];      // CSR row offsets (by dst)
__device__ int    g_bsum[MAXNB + 8];    // scan block sums
__device__ int    g_csr_src[MAXE];      // src ids grouped by dst
__device__ float  g_el1[MAXN];
__device__ float  g_er1[MAXN];
__device__ float4 g_z1[MAXN * 16];      // z1: N x 64 (head 0 only)
__device__ float  g_el2[MAXN];
__device__ float  g_er2[MAXN];
__device__ float  g_z2[MAXN * 30];      // z2: N x 30 (head (0,0) only)
__device__ float  g_part[MAXBLK * 32];  // per-block partial sums (layer-2 mean)

// -------------------- CSR build --------------------
__global__ void k_zero(int n) {
    int i = blockIdx.x * blockDim.x + threadIdx.x;
    if (i < n) g_deg[i] = 0;
}

__global__ void k_deg(const int* __restrict__ dst, int e) {
    int i = blockIdx.x * blockDim.x + threadIdx.x;
    if (i < e) atomicAdd(&g_deg[dst[i]], 1);
}

__global__ void k_scan1(int n) {
    __shared__ int sh[SCAN_BS];
    int t = threadIdx.x;
    int i = blockIdx.x * SCAN_BS + t;
    int v = (i < n) ? g_deg[i] : 0;
    sh[t] = v;
    __syncthreads();
    #pragma unroll
    for (int d = 1; d < SCAN_BS; d <<= 1) {
        int add = (t >= d) ? sh[t - d] : 0;
        __syncthreads();
        sh[t] += add;
        __syncthreads();
    }
    if (i < n) g_off[i] = sh[t] - v;          // block-local exclusive
    if (t == SCAN_BS - 1) g_bsum[blockIdx.x] = sh[t];
}

__global__ void k_scan2(int nb) {
    __shared__ int sh[256];
    int t = threadIdx.x;
    int v = (t < nb) ? g_bsum[t] : 0;
    sh[t] = v;
    __syncthreads();
    #pragma unroll
    for (int d = 1; d < 256; d <<= 1) {
        int add = (t >= d) ? sh[t - d] : 0;
        __syncthreads();
        sh[t] += add;
        __syncthreads();
    }
    if (t < nb) g_bsum[t] = sh[t] - v;        // exclusive prefix of block sums
}

__global__ void k_scan3(int n, int e) {
    int i = blockIdx.x * blockDim.x + threadIdx.x;
    if (i < n) {
        int ofs = g_off[i] + g_bsum[i >> 9];  // SCAN_BS == 512
        g_off[i] = ofs;
        g_deg[i] = ofs;                        // scatter cursor
    }
    if (i == 0) g_off[n] = e;
}

__global__ void k_scatter(const int* __restrict__ src, const int* __restrict__ dst, int e) {
    int i = blockIdx.x * blockDim.x + threadIdx.x;
    if (i < e) {
        int pos = atomicAdd(&g_deg[dst[i]], 1);
        g_csr_src[pos] = src[i];
    }
}

// -------------------- Layer 1 node features (head 0 only) --------------------
// z1[n] = feat[n] @ W1[:, 0:64];  el1 = z1·al1[0];  er1 = z1·ar1[0]
__global__ void k_node1(const float* __restrict__ feat, const float* __restrict__ W1,
                        const float* __restrict__ al1, const float* __restrict__ ar1, int n) {
    int i = blockIdx.x * blockDim.x + threadIdx.x;
    if (i >= n) return;
    float f0 = feat[3 * i], f1 = feat[3 * i + 1], f2 = feat[3 * i + 2];
    float el = 0.f, er = 0.f;
    float4* zo = &g_z1[i * 16];
    #pragma unroll
    for (int q = 0; q < 16; q++) {
        int k = 4 * q;
        float4 z;
        z.x = f0 * __ldg(W1 + k + 0) + f1 * __ldg(W1 + 128 + k + 0) + f2 * __ldg(W1 + 256 + k + 0);
        z.y = f0 * __ldg(W1 + k + 1) + f1 * __ldg(W1 + 128 + k + 1) + f2 * __ldg(W1 + 256 + k + 1);
        z.z = f0 * __ldg(W1 + k + 2) + f1 * __ldg(W1 + 128 + k + 2) + f2 * __ldg(W1 + 256 + k + 2);
        z.w = f0 * __ldg(W1 + k + 3) + f1 * __ldg(W1 + 128 + k + 3) + f2 * __ldg(W1 + 256 + k + 3);
        el += z.x * __ldg(al1 + k) + z.y * __ldg(al1 + k + 1) + z.z * __ldg(al1 + k + 2) + z.w * __ldg(al1 + k + 3);
        er += z.x * __ldg(ar1 + k) + z.y * __ldg(ar1 + k + 1) + z.z * __ldg(ar1 + k + 2) + z.w * __ldg(ar1 + k + 3);
        zo[q] = z;
    }
    g_el1[i] = el;
    g_er1[i] = er;
}

// -------------------- Layer 1 aggregation + layer 2 node features --------------------
// One warp per dst node: fused edge softmax (no max-pass) + weighted sum,
// then r1 = relu(out + b1[0]) held in regs/shared, z2 = r1 @ W2[:, :30], el2/er2.
__global__ void k_agg1(const float* __restrict__ b1, const float* __restrict__ W2,
                       const float* __restrict__ al2, const float* __restrict__ ar2, int n) {
    __shared__ float sh[AGG_WARPS][64];
    int wid = (blockIdx.x * blockDim.x + threadIdx.x) >> 5;
    int lane = threadIdx.x & 31;
    int ws = threadIdx.x >> 5;
    if (wid >= n) return;
    int o0 = g_off[wid], o1 = g_off[wid + 1];
    float ern = g_er1[wid];
    float den = 0.f, ax = 0.f, ay = 0.f;
    const float2* z1 = (const float2*)g_z1;
    for (int o = o0; o < o1; o++) {
        int s = __ldg(&g_csr_src[o]);
        float e = __ldg(&g_el1[s]) + ern;
        float w = __expf(e > 0.f ? e : 0.2f * e);
        float2 z = __ldg(&z1[s * 32 + lane]);
        den += w;
        ax += w * z.x;
        ay += w * z.y;
    }
    float inv = (o1 > o0) ? (1.0f / den) : 0.f;
    float rx = fmaxf(ax * inv + __ldg(b1 + 2 * lane), 0.f);
    float ry = fmaxf(ay * inv + __ldg(b1 + 2 * lane + 1), 0.f);
    sh[ws][2 * lane] = rx;
    sh[ws][2 * lane + 1] = ry;
    __syncwarp();
    float z2v = 0.f;
    if (lane < 30) {
        #pragma unroll
        for (int k = 0; k < 64; k++) z2v += sh[ws][k] * __ldg(W2 + k * 60 + lane);
        g_z2[wid * 30 + lane] = z2v;
    }
    float a = (lane < 30) ? z2v * __ldg(al2 + lane) : 0.f;
    float b = (lane < 30) ? z2v * __ldg(ar2 + lane) : 0.f;
    #pragma unroll
    for (int d = 16; d; d >>= 1) {
        a += __shfl_down_sync(0xffffffffu, a, d);
        b += __shfl_down_sync(0xffffffffu, b, d);
    }
    if (lane == 0) {
        g_el2[wid] = a;
        g_er2[wid] = b;
    }
}

// -------------------- Layer 2 aggregation -> global mean partials --------------------
__global__ void k_agg2(int n) {
    __shared__ float bs[32];
    int t = threadIdx.x;
    if (t < 32) bs[t] = 0.f;
    __syncthreads();
    int wid = (blockIdx.x * blockDim.x + t) >> 5;
    int lane = t & 31;
    if (wid < n) {
        int o0 = g_off[wid], o1 = g_off[wid + 1];
        float ern = g_er2[wid];
        float den = 0.f, acc = 0.f;
        for (int o = o0; o < o1; o++) {
            int s = __ldg(&g_csr_src[o]);
            float e = __ldg(&g_el2[s]) + ern;
            float w = __expf(e > 0.f ? e : 0.2f * e);
            den += w;
            float zv = (lane < 30) ? __ldg(&g_z2[s * 30 + lane]) : 0.f;
            acc += w * zv;
        }
        if (o1 > o0 && lane < 30) atomicAdd(&bs[lane], acc / den);
    }
    __syncthreads();
    if (t < 32) g_part[blockIdx.x * 32 + t] = bs[t];
}

// -------------------- Final: reduce partials + scalar tail + log_softmax --------------------
__global__ void k_final(const float* __restrict__ x, const float* __restrict__ vocab,
                        const float* __restrict__ W_lin1, const float* __restrict__ w2c,
                        const float* __restrict__ w3c, const float* __restrict__ W_lin4,
                        const float* __restrict__ b2, float* __restrict__ out,
                        int n, int nparts) {
    __shared__ float s30[32];
    __shared__ float hi[32];
    __shared__ float hv[72];
    __shared__ float xs[512];
    __shared__ float lg[2];
    int t = threadIdx.x;
    if (t < 32) s30[t] = 0.f;
    if (t < 512) xs[t] = x[t];
    __syncthreads();
    // reduce g_part[nparts][32]
    {
        float acc = 0.f;
        int j = t & 31;
        for (int bb = t >> 5; bb < nparts; bb += 32) acc += g_part[bb * 32 + j];
        atomicAdd(&s30[j], acc);
    }
    // h_i = W_lin1 @ x : one warp per output row
    int w = t >> 5, lane = t & 31;
    if (w < 30) {
        float p = 0.f;
        for (int k = lane; k < 512; k += 32) p += xs[k] * __ldg(W_lin1 + w * 512 + k);
        #pragma unroll
        for (int d = 16; d; d >>= 1) p += __shfl_down_sync(0xffffffffu, p, d);
        if (lane == 0) hi[w] = p;
    }
    __syncthreads();
    if (t < 30) {
        hv[t] = s30[t] / (float)n + b2[t];           // a[0,0]
        float h = hi[t], a = 0.f;
        for (int i2 = 0; i2 < 64; i2++) {
            float s2 = 1.f / (1.f + expf(-w2c[i2] * h));
            a += w3c[i2] * s2;
        }
        hv[30 + t] = 1.f / (1.f + expf(-a));          // h_img
    }
    if (t >= 32 && t < 42) hv[60 + (t - 32)] = vocab[t - 32];
    __syncthreads();
    if (t < 2) {
        float l = 0.f;
        for (int k = 0; k < 70; k++) l += __ldg(W_lin4 + t * 70 + k) * hv[k];
        lg[t] = l;
    }
    __syncthreads();
    if (t < 2) {
        float m = fmaxf(lg[0], lg[1]);
        float lse = m + logf(expf(lg[0] - m) + expf(lg[1] - m));
        out[t] = lg[t] - lse;
    }
}

extern "C" void kernel_launch(void* const* d_in, const int* in_sizes, int n_in,
                              void* d_out, int out_size) {
    const float* x      = (const float*)d_in[0];
    const float* feat   = (const float*)d_in[1];
    const float* vocab  = (const float*)d_in[2];
    const int*   src    = (const int*)d_in[3];
    const int*   dst    = (const int*)d_in[4];
    const float* W_lin1 = (const float*)d_in[5];
    const float* w_c2   = (const float*)d_in[6];
    const float* w_c3   = (const float*)d_in[7];
    const float* W_lin4 = (const float*)d_in[8];
    const float* W1     = (const float*)d_in[9];
    const float* al1    = (const float*)d_in[10];
    const float* ar1    = (const float*)d_in[11];
    const float* b1     = (const float*)d_in[12];
    const float* W2     = (const float*)d_in[13];
    const float* al2    = (const float*)d_in[14];
    const float* ar2    = (const float*)d_in[15];
    const float* b2     = (const float*)d_in[16];

    int N = in_sizes[1] / 3;
    int E = in_sizes[3];
    int nb = (N + SCAN_BS - 1) / SCAN_BS;
    int aggblk = (N + AGG_WARPS - 1) / AGG_WARPS;

    k_zero<<<(N + 1023) / 1024, 1024>>>(N);
    k_deg<<<(E + 255) / 256, 256>>>(dst, E);
    k_scan1<<<nb, SCAN_BS>>>(N);
    k_scan2<<<1, 256>>>(nb);
    k_scan3<<<(N + 255) / 256, 256>>>(N, E);
    k_scatter<<<(E + 255) / 256, 256>>>(src, dst, E);
    k_node1<<<(N + 255) / 256, 256>>>(feat, W1, al1, ar1, N);
    k_agg1<<<aggblk, AGG_WARPS * 32>>>(b1, W2, al2, ar2, N);
    k_agg2<<<aggblk, AGG_WARPS * 32>>>(N);
    k_final<<<1, 1024>>>(x, vocab, W_lin1, w_c2, w_c3, W_lin4, b2, (float*)d_out, N, aggblk);
}

// round 4
// speedup vs baseline: 1.0117x; 1.0117x over previous
#include <cuda_runtime.h>
#include <cuda_fp16.h>

// Problem-size capacities (N=100000, E=1000000 in this dataset)
#define MAXN 100352
#define MAXE 1000448
#define SCAN_BS 512
#define MAXNB ((MAXN + SCAN_BS - 1) / SCAN_BS)   // 196 <= 256
#define AGG_WARPS 8
#define NBLK2 1184                                // grid-stride blocks for k_agg2 (148*8)

// ---- device scratch (static: no allocations allowed) ----
__device__ int     g_deg[MAXN];           // degree, then scatter cursor
__device__ int     g_off[MAXN + 1];       // CSR row offsets (by dst)
__device__ int     g_bsum[MAXNB + 8];     // scan block sums
__device__ int     g_csr_src[MAXE];       // src ids grouped by dst
__device__ float   g_el1[MAXN];
__device__ float   g_er1[MAXN];
__device__ __half2 g_z1h[MAXN * 32];      // z1: N x 64 fp16 (head 0 only), 128B/node
__device__ float   g_el2[MAXN];
__device__ float   g_er2[MAXN];
__device__ __half2 g_z2h[MAXN * 16];      // z2: N x 32 fp16 (30 used), 64B/node
__device__ float   g_part[NBLK2 * 32];    // per-block partial sums (layer-2 mean)

// -------------------- degree count + layer-1 node features (fused) --------------------
// Blocks [0, degBlocks): atomic degree histogram over dst.
// Blocks [degBlocks, ...): z1 = feat @ W1[:, 0:64] (fp32), el1/er1 (fp32), z1 stored fp16.
__global__ void k_deg_node1(const int* __restrict__ dst, int e, int degBlocks,
                            const float* __restrict__ feat, const float* __restrict__ W1,
                            const float* __restrict__ al1, const float* __restrict__ ar1, int n) {
    if (blockIdx.x < degBlocks) {
        int i = blockIdx.x * blockDim.x + threadIdx.x;
        if (i < e) atomicAdd(&g_deg[dst[i]], 1);
        return;
    }
    int i = (blockIdx.x - degBlocks) * blockDim.x + threadIdx.x;
    if (i >= n) return;
    float f0 = feat[3 * i], f1 = feat[3 * i + 1], f2 = feat[3 * i + 2];
    float el = 0.f, er = 0.f;
    __half2* zo = &g_z1h[i * 32];
    #pragma unroll
    for (int q = 0; q < 32; q++) {
        int k = 2 * q;
        float za = f0 * __ldg(W1 + k)     + f1 * __ldg(W1 + 128 + k)     + f2 * __ldg(W1 + 256 + k);
        float zb = f0 * __ldg(W1 + k + 1) + f1 * __ldg(W1 + 128 + k + 1) + f2 * __ldg(W1 + 256 + k + 1);
        el += za * __ldg(al1 + k) + zb * __ldg(al1 + k + 1);
        er += za * __ldg(ar1 + k) + zb * __ldg(ar1 + k + 1);
        zo[q] = __floats2half2_rn(za, zb);
    }
    g_el1[i] = el;
    g_er1[i] = er;
}

// -------------------- scans (shuffle-based) --------------------
__global__ void k_scan1(int n) {
    __shared__ int ws[16];
    int t = threadIdx.x;
    int i = blockIdx.x * SCAN_BS + t;
    int v = (i < n) ? g_deg[i] : 0;
    int x = v;
    #pragma unroll
    for (int d = 1; d < 32; d <<= 1) {
        int y = __shfl_up_sync(0xffffffffu, x, d);
        if ((t & 31) >= d) x += y;
    }
    if ((t & 31) == 31) ws[t >> 5] = x;
    __syncthreads();
    if (t < 16) {
        int y = ws[t];
        #pragma unroll
        for (int d = 1; d < 16; d <<= 1) {
            int z = __shfl_up_sync(0x0000ffffu, y, d);
            if (t >= d) y += z;
        }
        ws[t] = y;
    }
    __syncthreads();
    int base = (t >= 32) ? ws[(t >> 5) - 1] : 0;
    int incl = base + x;
    if (i < n) g_off[i] = incl - v;           // block-local exclusive
    if (t == SCAN_BS - 1) g_bsum[blockIdx.x] = incl;
}

__global__ void k_scan2(int nb) {
    __shared__ int ws[8];
    int t = threadIdx.x;                       // 256 threads
    int v = (t < nb) ? g_bsum[t] : 0;
    int x = v;
    #pragma unroll
    for (int d = 1; d < 32; d <<= 1) {
        int y = __shfl_up_sync(0xffffffffu, x, d);
        if ((t & 31) >= d) x += y;
    }
    if ((t & 31) == 31) ws[t >> 5] = x;
    __syncthreads();
    if (t < 8) {
        int y = ws[t];
        #pragma unroll
        for (int d = 1; d < 8; d <<= 1) {
            int z = __shfl_up_sync(0x000000ffu, y, d);
            if (t >= d) y += z;
        }
        ws[t] = y;
    }
    __syncthreads();
    int base = (t >= 32) ? ws[(t >> 5) - 1] : 0;
    if (t < nb) g_bsum[t] = base + x - v;      // exclusive prefix of block sums
}

__global__ void k_scan3(int n, int e) {
    int i = blockIdx.x * blockDim.x + threadIdx.x;
    if (i < n) {
        int ofs = g_off[i] + g_bsum[i >> 9];   // SCAN_BS == 512
        g_off[i] = ofs;
        g_deg[i] = ofs;                         // scatter cursor
    }
    if (i == 0) g_off[n] = e;
}

__global__ void k_scatter(const int* __restrict__ src, const int* __restrict__ dst, int e) {
    int i = blockIdx.x * blockDim.x + threadIdx.x;
    if (i < e) {
        int pos = atomicAdd(&g_deg[dst[i]], 1);
        g_csr_src[pos] = src[i];
    }
}

// -------------------- Layer 1 aggregation + layer 2 node features --------------------
// One warp per dst node: fused edge softmax (no max-pass) + weighted sum (z1 fp16 gather),
// then r1 = relu(out + b1[0]), z2 = r1 @ W2[:, :30] (fp32), stored fp16 padded to 32.
__global__ void k_agg1(const float* __restrict__ b1, const float* __restrict__ W2,
                       const float* __restrict__ al2, const float* __restrict__ ar2, int n) {
    __shared__ float sh[AGG_WARPS][64];
    int wid = (blockIdx.x * blockDim.x + threadIdx.x) >> 5;
    int lane = threadIdx.x & 31;
    int ws = threadIdx.x >> 5;
    if (wid >= n) return;
    int o0 = g_off[wid], o1 = g_off[wid + 1];
    float ern = g_er1[wid];
    float den = 0.f, ax = 0.f, ay = 0.f;
    for (int o = o0; o < o1; o++) {
        int s = __ldg(&g_csr_src[o]);
        float e = __ldg(&g_el1[s]) + ern;
        float w = __expf(e > 0.f ? e : 0.2f * e);
        float2 z = __half22float2(__ldg(&g_z1h[s * 32 + lane]));
        den += w;
        ax += w * z.x;
        ay += w * z.y;
    }
    float inv = (o1 > o0) ? (1.0f / den) : 0.f;
    float rx = fmaxf(ax * inv + __ldg(b1 + 2 * lane), 0.f);
    float ry = fmaxf(ay * inv + __ldg(b1 + 2 * lane + 1), 0.f);
    sh[ws][2 * lane] = rx;
    sh[ws][2 * lane + 1] = ry;
    __syncwarp();
    float z2v = 0.f;
    if (lane < 30) {
        #pragma unroll
        for (int k = 0; k < 64; k++) z2v += sh[ws][k] * __ldg(W2 + k * 60 + lane);
    }
    // el2/er2 from fp32 z2
    float a = (lane < 30) ? z2v * __ldg(al2 + lane) : 0.f;
    float b = (lane < 30) ? z2v * __ldg(ar2 + lane) : 0.f;
    #pragma unroll
    for (int d = 16; d; d >>= 1) {
        a += __shfl_down_sync(0xffffffffu, a, d);
        b += __shfl_down_sync(0xffffffffu, b, d);
    }
    if (lane == 0) {
        g_el2[wid] = a;
        g_er2[wid] = b;
    }
    // pack z2 to fp16 pairs: lane l < 16 stores components (2l, 2l+1)
    float p0 = __shfl_sync(0xffffffffu, z2v, 2 * lane);
    float p1 = __shfl_sync(0xffffffffu, z2v, 2 * lane + 1);
    if (lane < 16) g_z2h[wid * 16 + lane] = __floats2half2_rn(p0, p1);
}

// -------------------- Layer 2 aggregation -> global mean partials --------------------
// Grid-stride over nodes; per-warp register accumulation, one shared atomic per warp.
__global__ void k_agg2(int n) {
    __shared__ float bs[32];
    int t = threadIdx.x;
    if (t < 32) bs[t] = 0.f;
    __syncthreads();
    int lane = t & 31;
    int warp0 = (blockIdx.x * blockDim.x + t) >> 5;
    int nwarps = (gridDim.x * blockDim.x) >> 5;
    float sx = 0.f, sy = 0.f;
    for (int wid = warp0; wid < n; wid += nwarps) {
        int o0 = g_off[wid], o1 = g_off[wid + 1];
        if (o0 >= o1) continue;
        float ern = g_er2[wid];
        float den = 0.f, ax = 0.f, ay = 0.f;
        for (int o = o0; o < o1; o++) {
            int s = __ldg(&g_csr_src[o]);
            float e = __ldg(&g_el2[s]) + ern;
            float w = __expf(e > 0.f ? e : 0.2f * e);
            den += w;
            if (lane < 16) {
                float2 z = __half22float2(__ldg(&g_z2h[s * 16 + lane]));
                ax += w * z.x;
                ay += w * z.y;
            }
        }
        float inv = 1.0f / den;
        sx += ax * inv;
        sy += ay * inv;
    }
    if (lane < 16) {
        atomicAdd(&bs[2 * lane], sx);
        atomicAdd(&bs[2 * lane + 1], sy);
    }
    __syncthreads();
    if (t < 32) g_part[blockIdx.x * 32 + t] = bs[t];
}

// -------------------- Final: reduce partials + scalar tail + log_softmax --------------------
__global__ void k_final(const float* __restrict__ x, const float* __restrict__ vocab,
                        const float* __restrict__ W_lin1, const float* __restrict__ w2c,
                        const float* __restrict__ w3c, const float* __restrict__ W_lin4,
                        const float* __restrict__ b2, float* __restrict__ out,
                        int n, int nparts) {
    __shared__ float s30[32];
    __shared__ float hi[32];
    __shared__ float hv[72];
    __shared__ float xs[512];
    __shared__ float lg[2];
    int t = threadIdx.x;
    if (t < 32) s30[t] = 0.f;
    if (t < 512) xs[t] = x[t];
    __syncthreads();
    // reduce g_part[nparts][32]
    {
        float acc = 0.f;
        int j = t & 31;
        for (int bb = t >> 5; bb < nparts; bb += 32) acc += g_part[bb * 32 + j];
        atomicAdd(&s30[j], acc);
    }
    // h_i = W_lin1 @ x : one warp per output row
    int w = t >> 5, lane = t & 31;
    if (w < 30) {
        float p = 0.f;
        for (int k = lane; k < 512; k += 32) p += xs[k] * __ldg(W_lin1 + w * 512 + k);
        #pragma unroll
        for (int d = 16; d; d >>= 1) p += __shfl_down_sync(0xffffffffu, p, d);
        if (lane == 0) hi[w] = p;
    }
    __syncthreads();
    if (t < 30) {
        hv[t] = s30[t] / (float)n + b2[t];            // a[0,0]
        float h = hi[t], a = 0.f;
        for (int i2 = 0; i2 < 64; i2++) {
            float s2 = 1.f / (1.f + expf(-w2c[i2] * h));
            a += w3c[i2] * s2;
        }
        hv[30 + t] = 1.f / (1.f + expf(-a));           // h_img
    }
    if (t >= 32 && t < 42) hv[60 + (t - 32)] = vocab[t - 32];
    __syncthreads();
    if (t < 2) {
        float l = 0.f;
        for (int k = 0; k < 70; k++) l += __ldg(W_lin4 + t * 70 + k) * hv[k];
        lg[t] = l;
    }
    __syncthreads();
    if (t < 2) {
        float m = fmaxf(lg[0], lg[1]);
        float lse = m + logf(expf(lg[0] - m) + expf(lg[1] - m));
        out[t] = lg[t] - lse;
    }
}

extern "C" void kernel_launch(void* const* d_in, const int* in_sizes, int n_in,
                              void* d_out, int out_size) {
    const float* x      = (const float*)d_in[0];
    const float* feat   = (const float*)d_in[1];
    const float* vocab  = (const float*)d_in[2];
    const int*   src    = (const int*)d_in[3];
    const int*   dst    = (const int*)d_in[4];
    const float* W_lin1 = (const float*)d_in[5];
    const float* w_c2   = (const float*)d_in[6];
    const float* w_c3   = (const float*)d_in[7];
    const float* W_lin4 = (const float*)d_in[8];
    const float* W1     = (const float*)d_in[9];
    const float* al1    = (const float*)d_in[10];
    const float* ar1    = (const float*)d_in[11];
    const float* b1     = (const float*)d_in[12];
    const float* W2     = (const float*)d_in[13];
    const float* al2    = (const float*)d_in[14];
    const float* ar2    = (const float*)d_in[15];
    const float* b2     = (const float*)d_in[16];

    int N = in_sizes[1] / 3;
    int E = in_sizes[3];
    int nb = (N + SCAN_BS - 1) / SCAN_BS;
    int degBlocks  = (E + 255) / 256;
    int nodeBlocks = (N + 255) / 256;
    int aggblk = (N + AGG_WARPS - 1) / AGG_WARPS;

    void* degPtr = nullptr;
    cudaGetSymbolAddress(&degPtr, g_deg);
    cudaMemsetAsync(degPtr, 0, (size_t)N * sizeof(int), 0);

    k_deg_node1<<<degBlocks + nodeBlocks, 256>>>(dst, E, degBlocks, feat, W1, al1, ar1, N);
    k_scan1<<<nb, SCAN_BS>>>(N);
    k_scan2<<<1, 256>>>(nb);
    k_scan3<<<(N + 255) / 256, 256>>>(N, E);
    k_scatter<<<(E + 255) / 256, 256>>>(src, dst, E);
    k_agg1<<<aggblk, AGG_WARPS * 32>>>(b1, W2, al2, ar2, N);
    k_agg2<<<NBLK2, AGG_WARPS * 32>>>(N);
    k_final<<<1, 1024>>>(x, vocab, W_lin1, w_c2, w_c3, W_lin4, b2, (float*)d_out, N, NBLK2);
}